// round 14
// baseline (speedup 1.0000x reference)
#include <cuda_runtime.h>
#include <cstdint>
#include <cstring>

#define T_LEN  2048
#define HID    300
#define DIN    320     // 300 emb + 20 other feats
#define G4     1200    // 4*HID gate rows
#define NTAGS  12
#define START_TAG 10
#define STOP_TAG  11
#define NEGV  (-10000.0f)

// ---------------- scratch (static device memory; no allocation) ----------------
__device__ float g_X [T_LEN * DIN];            // concat(emb[idx], other) [T, 320]
__device__ float g_A [2 * T_LEN * G4];         // x @ Wi^T + bi + bh, per direction
__device__ float g_HS[2 * T_LEN * HID];        // hidden states (bw stored at original t)
__device__ float g_F [T_LEN * NTAGS];          // emission feats

// ---------------- 1) embedding gather + feature concat ----------------
__global__ void gather_kernel(const int* __restrict__ idx,
                              const float* __restrict__ emb,
                              const float* __restrict__ other) {
    const int t = blockIdx.x;
    const int j = threadIdx.x;            // 0..319
    float v;
    if (j < HID) v = emb[(size_t)idx[t] * HID + j];
    else         v = other[t * 20 + (j - HID)];
    g_X[t * DIN + j] = v;
}

// ---------------- 2) input GEMM: A[dir][t][r] = X[t]·Wi[r] + bi[r] + bh[r] ----
// M=2048 (t), N=1200 (r), K=320. Tiles 64x64x32, 256 threads, 4x4 microtile.
__global__ void __launch_bounds__(256) gemm_in_kernel(
    const float* __restrict__ Wf, const float* __restrict__ Wb,
    const float* __restrict__ bif, const float* __restrict__ bhf,
    const float* __restrict__ bib, const float* __restrict__ bhb) {
    const int dir = blockIdx.z;
    const float* __restrict__ W  = dir ? Wb  : Wf;
    const float* __restrict__ b1 = dir ? bib : bif;
    const float* __restrict__ b2 = dir ? bhb : bhf;
    float* __restrict__ A = g_A + (size_t)dir * T_LEN * G4;

    __shared__ __align__(16) float Xs[32][68];  // [k][m]
    __shared__ __align__(16) float Ws[32][68];  // [k][n]

    const int tid = threadIdx.x;
    const int tx = tid & 15, ty = tid >> 4;
    const int m0 = blockIdx.y * 64, n0 = blockIdx.x * 64;

    float acc[4][4];
#pragma unroll
    for (int i = 0; i < 4; i++)
#pragma unroll
        for (int j = 0; j < 4; j++) acc[i][j] = 0.f;

    for (int k0 = 0; k0 < DIN; k0 += 32) {
#pragma unroll
        for (int it = 0; it < 2; ++it) {
            int v   = tid + it * 256;   // 0..511 float4 slots per tile
            int row = v >> 3;           // 0..63
            int c4  = v & 7;            // float4 within 32-wide k chunk
            float4 x4 = *(const float4*)&g_X[(size_t)(m0 + row) * DIN + k0 + c4 * 4];
            Xs[c4 * 4 + 0][row] = x4.x; Xs[c4 * 4 + 1][row] = x4.y;
            Xs[c4 * 4 + 2][row] = x4.z; Xs[c4 * 4 + 3][row] = x4.w;
            int wr = n0 + row;
            float4 w4 = make_float4(0.f, 0.f, 0.f, 0.f);
            if (wr < G4) w4 = *(const float4*)&W[(size_t)wr * DIN + k0 + c4 * 4];
            Ws[c4 * 4 + 0][row] = w4.x; Ws[c4 * 4 + 1][row] = w4.y;
            Ws[c4 * 4 + 2][row] = w4.z; Ws[c4 * 4 + 3][row] = w4.w;
        }
        __syncthreads();
#pragma unroll
        for (int kk = 0; kk < 32; kk++) {
            float4 xr = *(const float4*)&Xs[kk][ty * 4];
            float4 wr = *(const float4*)&Ws[kk][tx * 4];
            float xv[4] = {xr.x, xr.y, xr.z, xr.w};
            float wv[4] = {wr.x, wr.y, wr.z, wr.w};
#pragma unroll
            for (int i = 0; i < 4; i++)
#pragma unroll
                for (int j = 0; j < 4; j++) acc[i][j] = fmaf(xv[i], wv[j], acc[i][j]);
        }
        __syncthreads();
    }
#pragma unroll
    for (int i = 0; i < 4; i++) {
        int m = m0 + ty * 4 + i;
#pragma unroll
        for (int j = 0; j < 4; j++) {
            int n = n0 + tx * 4 + j;
            if (n < G4) A[(size_t)m * G4 + n] = acc[i][j] + b1[n] + b2[n];
        }
    }
}

// ---- mbarrier helpers (cluster-scope acquire wait) ----
#define MBAR_WAIT_ACQ_CLUSTER(mbar_u32, parity) do {                                 \
    unsigned _done;                                                                   \
    asm volatile("{\n\t.reg .pred p;\n\t"                                             \
        "mbarrier.try_wait.parity.acquire.cluster.shared::cta.b64 p, [%1], %2;\n\t"   \
        "selp.b32 %0, 1, 0, p;\n\t}"                                                  \
        : "=r"(_done) : "r"(mbar_u32), "r"(parity) : "memory");                       \
    if (!_done) {                                                                     \
        asm volatile("{\n\t.reg .pred P1;\n\t"                                        \
            "WL_%=:\n\t"                                                              \
            "mbarrier.try_wait.parity.acquire.cluster.shared::cta.b64 P1, [%0], %1, 0x989680;\n\t" \
            "@P1 bra.uni WD_%=;\n\t"                                                  \
            "bra.uni WL_%=;\n\t"                                                      \
            "WD_%=:\n\t}"                                                             \
            :: "r"(mbar_u32), "r"(parity) : "memory");                                \
    }                                                                                 \
} while (0)

// ---------------- 3) BiLSTM recurrence: 2 clusters x 8 CTAs x 512 threads ------
// CTA rank c owns hidden slice [start, start+Hc): ranks 0-3 Hc=38, ranks 4-7 Hc=37.
// 15 active warps = 3 k-chunks (100 floats) x 5 row-warps; warp 15 idle.
// Wh slice lives in registers as 50 packed f32x2. h broadcast via LDS.128; new h
// pushed to all CTAs via DSMEM stores, signalled with per-buffer mbarriers
// (count=8, one release-arrive per producing CTA) instead of a full cluster
// barrier -> no per-step rendezvous, no CCTL.IVALL L1 flush, sleep-wait wakeup.
__global__ __launch_bounds__(512, 1) __cluster_dims__(8, 1, 1)
void lstm_kernel(const float* __restrict__ Whf, const float* __restrict__ Whb,
                 const float* __restrict__ h0,  const float* __restrict__ c0) {
    const int dir = blockIdx.x >> 3;
    unsigned crank;
    asm("mov.u32 %0, %%cluster_ctarank;" : "=r"(crank));
    const int Hc    = (crank < 4) ? 38 : 37;
    const int start = (crank < 4) ? 38 * (int)crank : 152 + 37 * ((int)crank - 4);
    const int NROWS = 4 * Hc;

    const float* __restrict__ Wh    = dir ? Whb : Whf;
    const float* __restrict__ Abase = g_A  + (size_t)dir * T_LEN * G4;
    float*       __restrict__ HS    = g_HS + (size_t)dir * T_LEN * HID;

    __shared__ __align__(16) float hbuf[2][300];   // h double buffer (300 = 3*100)
    __shared__ float part[3][160];                 // per-k-chunk partial sums
    __shared__ float a_s[160];                     // staged input activations
    __shared__ __align__(8) unsigned long long mbars[2];  // guards hbuf[0]/hbuf[1]

    const int tid  = threadIdx.x;
    const int w    = tid >> 5, lane = tid & 31;
    const bool wact = (w < 15);
    const int q    = wact ? (w / 5) : 0;           // k-chunk 0..2
    const int rw   = w % 5;                        // row-warp 0..4
    const int rloc = rw * 32 + lane;               // 0..159
    const bool active = wact && (rloc < NROWS);

    int gg = 0, kk = 0;
    if (active) { gg = rloc / Hc; kk = rloc - gg * Hc; }
    const int rglobal = gg * HID + start + kk;     // gate row 0..1199
    const bool loader = (q == 0) && active;        // this thread fetches A each step

    // preload Wh slice into registers as 50 packed f32x2 (zeros when inactive)
    unsigned long long w2[50];
    {
        const float* wrow = Wh + (size_t)rglobal * HID + q * 100;
#pragma unroll
        for (int i = 0; i < 25; i++) {
            float4 wv = make_float4(0.f, 0.f, 0.f, 0.f);
            if (active) wv = *(const float4*)(wrow + i * 4);
            unsigned long long lo, hi;
            memcpy(&lo, &wv.x, 8); memcpy(&hi, &wv.z, 8);
            w2[2 * i] = lo; w2[2 * i + 1] = hi;
        }
    }

    // shared-space addresses (loop-invariant)
    unsigned la0 = 0, la1 = 0;
    if (tid < Hc) {
        asm("{ .reg .u64 u; cvta.to.shared.u64 u, %1; cvt.u32.u64 %0, u; }"
            : "=r"(la0) : "l"((void*)&hbuf[0][start + tid]));
        asm("{ .reg .u64 u; cvta.to.shared.u64 u, %1; cvt.u32.u64 %0, u; }"
            : "=r"(la1) : "l"((void*)&hbuf[1][start + tid]));
    }
    unsigned mb0, mb1;
    asm("{ .reg .u64 u; cvta.to.shared.u64 u, %1; cvt.u32.u64 %0, u; }"
        : "=r"(mb0) : "l"((void*)&mbars[0]));
    asm("{ .reg .u64 u; cvta.to.shared.u64 u, %1; cvt.u32.u64 %0, u; }"
        : "=r"(mb1) : "l"((void*)&mbars[1]));

    // init mbarriers (count = 8: one arrive per producing CTA) + h buffers + c
    if (tid == 0) {
        asm volatile("mbarrier.init.shared.b64 [%0], 8;" :: "r"(mb0) : "memory");
        asm volatile("mbarrier.init.shared.b64 [%0], 8;" :: "r"(mb1) : "memory");
    }
    for (int j = tid; j < 300; j += 512) {
        hbuf[0][j] = h0[dir * HID + j];
        hbuf[1][j] = 0.f;
    }
    float creg = (tid < Hc) ? c0[dir * HID + start + tid] : 0.f;
    __syncthreads();
    // one startup cluster sync: mbarrier inits must be visible before any
    // remote arrive targets them
    asm volatile("barrier.cluster.arrive.aligned;" ::: "memory");
    asm volatile("barrier.cluster.wait.aligned;"  ::: "memory");

    // prefetch A for step 0
    float a_val = 0.f;
    if (loader) a_val = __ldg(Abase + (size_t)(dir ? (T_LEN - 1) : 0) * G4 + rglobal);

    int ph0 = 0, ph1 = 0;
    for (int t = 0; t < T_LEN; ++t) {
        const int pc = t & 1;                      // consume hbuf[pc]
        // wait for all 8 CTAs' slices of this step's h (step 0: filled locally)
        if (t > 0) {
            if (pc == 0) { MBAR_WAIT_ACQ_CLUSTER(mb0, ph0); ph0 ^= 1; }
            else         { MBAR_WAIT_ACQ_CLUSTER(mb1, ph1); ph1 ^= 1; }
        }

        // GEMV partial: packed f32x2 FMA, h chunk via broadcast LDS.128
        const ulonglong2* hv = (const ulonglong2*)(&hbuf[pc][q * 100]);
        unsigned long long a0 = 0, a1 = 0;   // (0.0f,0.0f) bit pattern
#pragma unroll
        for (int i = 0; i < 25; i++) {
            ulonglong2 hh = hv[i];
            asm("fma.rn.f32x2 %0, %1, %2, %0;" : "+l"(a0) : "l"(w2[2 * i]),     "l"(hh.x));
            asm("fma.rn.f32x2 %0, %1, %2, %0;" : "+l"(a1) : "l"(w2[2 * i + 1]), "l"(hh.y));
        }
        if (wact) {
            float2 f0, f1;
            memcpy(&f0, &a0, 8); memcpy(&f1, &a1, 8);
            part[q][rloc] = (f0.x + f0.y) + (f1.x + f1.y);
            if (loader) a_s[rloc] = a_val;
        }
        __syncthreads();

        // prefetch next step's A value under the epilogue
        if (loader && t + 1 < T_LEN) {
            const int tN = dir ? (T_LEN - 2 - t) : (t + 1);
            a_val = __ldg(Abase + (size_t)tN * G4 + rglobal);
        }

        // epilogue lives in warps 0-1 (tid < Hc <= 38)
        if (tid < 64) {
            if (tid < Hc) {
                float pre[4];
#pragma unroll
                for (int g = 0; g < 4; g++) {
                    int r = g * Hc + tid;
                    pre[g] = a_s[r] + part[0][r] + part[1][r] + part[2][r];
                }
                float ig = __fdividef(1.f, 1.f + __expf(-pre[0]));
                float fg = __fdividef(1.f, 1.f + __expf(-pre[1]));
                float gv = 1.f - __fdividef(2.f, __expf(2.f * pre[2]) + 1.f);
                float og = __fdividef(1.f, 1.f + __expf(-pre[3]));
                creg = fg * creg + ig * gv;
                float hn = og * (1.f - __fdividef(2.f, __expf(2.f * creg) + 1.f));

                if (t + 1 < T_LEN) {
                    // push h element to every CTA's hbuf[pc^1] (incl. self)
                    unsigned la = pc ? la0 : la1;
#pragma unroll
                    for (int r = 0; r < 8; r++) {
                        unsigned ra;
                        asm("mapa.shared::cluster.u32 %0, %1, %2;" : "=r"(ra) : "r"(la), "r"(r));
                        asm volatile("st.shared::cluster.f32 [%0], %1;" :: "r"(ra), "f"(hn));
                    }
                }
                const int tA = dir ? (T_LEN - 1 - t) : t;
                HS[(size_t)tA * HID + start + tid] = hn;
            }
            // order all epilogue threads' cluster stores before the arrives
            asm volatile("bar.sync 1, 64;" ::: "memory");
            if (tid == 0 && t + 1 < T_LEN) {
                asm volatile("fence.acq_rel.cluster;" ::: "memory");
                unsigned mbn = pc ? mb0 : mb1;     // mbar guarding hbuf[pc^1]
#pragma unroll
                for (int r = 0; r < 8; r++) {
                    asm volatile(
                        "{ .reg .b32 ra;\n\t"
                        "mapa.shared::cluster.u32 ra, %0, %1;\n\t"
                        "mbarrier.arrive.release.cluster.shared::cluster.b64 _, [ra]; }"
                        :: "r"(mbn), "r"(r) : "memory");
                }
            }
        }
    }
    // drain: no remote traffic is issued for the final step; still rendezvous
    // once so no CTA's smem disappears while a straggler could touch it
    asm volatile("barrier.cluster.arrive.aligned;" ::: "memory");
    asm volatile("barrier.cluster.wait.aligned;"  ::: "memory");
}

// ---------------- 4) emission feats: feats[t][n] = concat(fw,bw)[t] . W_tag[n] + b
__global__ void __launch_bounds__(384) feats_kernel(const float* __restrict__ Wt,
                                                    const float* __restrict__ bt) {
    const int t = blockIdx.x;
    const int n = threadIdx.x >> 5;   // 0..11 (one warp per tag)
    const int lane = threadIdx.x & 31;
    const float* hf = g_HS + (size_t)t * HID;
    const float* hb = g_HS + (size_t)T_LEN * HID + (size_t)t * HID;
    float s = 0.f;
    for (int j = lane; j < 2 * HID; j += 32) {
        float v = (j < HID) ? hf[j] : hb[j - HID];
        s = fmaf(v, Wt[n * 2 * HID + j], s);
    }
#pragma unroll
    for (int o = 16; o; o >>= 1) s += __shfl_down_sync(0xffffffffu, s, o);
    if (lane == 0) g_F[t * NTAGS + n] = s + bt[n];
}

// ---------------- 5) Viterbi + backtrace: single warp ----------------
// Emission loads are distance-2 prefetched so the serial loop runs at the
// SHFL + select-tree compute floor.
__global__ void viterbi_kernel(const float* __restrict__ trans,
                               float* __restrict__ outf, int out_size) {
    __shared__ unsigned char bps[T_LEN * NTAGS];   // 24 KB backpointers
    const int lane = threadIdx.x;
    const bool on = lane < NTAGS;

    float trow[NTAGS];
#pragma unroll
    for (int pp = 0; pp < NTAGS; pp++) trow[pp] = on ? trans[lane * NTAGS + pp] : NEGV;
    float tstop = on ? trans[STOP_TAG * NTAGS + lane] : NEGV;
    float fv = (lane == START_TAG) ? 0.f : NEGV;

    const float* __restrict__ Fp = on ? (g_F + lane) : g_F;   // lane's column
    float featC = __ldg(Fp);                                   // feat(0)
    float featN = __ldg(Fp + NTAGS);                           // feat(1)

    for (int t = 0; t < T_LEN; t++) {
        float featP = (t + 2 < T_LEN) ? __ldg(Fp + (size_t)(t + 2) * NTAGS) : 0.f;

        float s[NTAGS];
#pragma unroll
        for (int pp = 0; pp < NTAGS; pp++)
            s[pp] = __shfl_sync(0xffffffffu, fv, pp) + trow[pp];

        // argmax with JAX first-index tie semantics (strict >, lower index wins)
        float v0 = s[0];  int i0 = 0;  if (s[1]  > v0) { v0 = s[1];  i0 = 1; }
        float v1 = s[2];  int i1 = 2;  if (s[3]  > v1) { v1 = s[3];  i1 = 3; }
        float v2 = s[4];  int i2 = 4;  if (s[5]  > v2) { v2 = s[5];  i2 = 5; }
        float v3 = s[6];  int i3 = 6;  if (s[7]  > v3) { v3 = s[7];  i3 = 7; }
        float v4 = s[8];  int i4 = 8;  if (s[9]  > v4) { v4 = s[9];  i4 = 9; }
        float v5 = s[10]; int i5 = 10; if (s[11] > v5) { v5 = s[11]; i5 = 11; }
        if (v1 > v0) { v0 = v1; i0 = i1; }
        if (v3 > v2) { v2 = v3; i2 = i3; }
        if (v5 > v4) { v4 = v5; i4 = i5; }
        if (v2 > v0) { v0 = v2; i0 = i2; }
        if (v4 > v0) { v0 = v4; i0 = i4; }

        if (on) {
            fv = v0 + featC;
            bps[t * NTAGS + lane] = (unsigned char)i0;
        }
        featC = featN;
        featN = featP;
    }

    float tv = fv + tstop;
    float best = __shfl_sync(0xffffffffu, tv, 0);
    int bi = 0;
#pragma unroll
    for (int pp = 1; pp < NTAGS; pp++) {
        float v = __shfl_sync(0xffffffffu, tv, pp);
        if (v > best) { best = v; bi = pp; }
    }

    if (lane == 0) {
        if (out_size == T_LEN + 1) {             // [score, path...] as float32
            outf[0] = best;
            int tg = bi;
            for (int t = T_LEN - 1; t >= 0; t--) {
                outf[1 + t] = (float)tg;
                tg = bps[t * NTAGS + tg];
            }
        } else {                                  // fallback: int32 path only
            int* oi = (int*)outf;
            int tg = bi;
            for (int t = T_LEN - 1; t >= 0; t--) {
                oi[t] = tg;
                tg = bps[t * NTAGS + tg];
            }
        }
    }
}

// ---------------- launch ----------------
extern "C" void kernel_launch(void* const* d_in, const int* in_sizes, int n_in,
                              void* d_out, int out_size) {
    const int*   indices = (const int*)  d_in[0];
    const float* other   = (const float*)d_in[1];
    const float* emb     = (const float*)d_in[2];
    const float* Wi_f    = (const float*)d_in[3];
    const float* Wh_f    = (const float*)d_in[4];
    const float* bi_f    = (const float*)d_in[5];
    const float* bh_f    = (const float*)d_in[6];
    const float* Wi_b    = (const float*)d_in[7];
    const float* Wh_b    = (const float*)d_in[8];
    const float* bi_b    = (const float*)d_in[9];
    const float* bh_b    = (const float*)d_in[10];
    const float* W_tag   = (const float*)d_in[11];
    const float* b_tag   = (const float*)d_in[12];
    const float* trans   = (const float*)d_in[13];
    const float* h0      = (const float*)d_in[14];
    const float* c0      = (const float*)d_in[15];

    gather_kernel<<<T_LEN, DIN>>>(indices, emb, other);
    gemm_in_kernel<<<dim3(19, 32, 2), 256>>>(Wi_f, Wi_b, bi_f, bh_f, bi_b, bh_b);
    lstm_kernel<<<16, 512>>>(Wh_f, Wh_b, h0, c0);
    feats_kernel<<<T_LEN, 384>>>(W_tag, b_tag);
    viterbi_kernel<<<1, 32>>>(trans, (float*)d_out, out_size);
}

// round 17
// speedup vs baseline: 2.0544x; 2.0544x over previous
#include <cuda_runtime.h>
#include <cstdint>
#include <cstring>

#define T_LEN  2048
#define HID    300
#define DIN    320     // 300 emb + 20 other feats
#define G4     1200    // 4*HID gate rows
#define NTAGS  12
#define START_TAG 10
#define STOP_TAG  11
#define NEGV  (-10000.0f)

// ---------------- scratch (static device memory; no allocation) ----------------
__device__ float g_X [T_LEN * DIN];            // concat(emb[idx], other) [T, 320]
__device__ float g_A [2 * T_LEN * G4];         // x @ Wi^T + bi + bh, per direction
__device__ float g_HS[2 * T_LEN * HID];        // hidden states (bw stored at original t)
__device__ float g_F [T_LEN * NTAGS];          // emission feats

// ---------------- 1) embedding gather + feature concat ----------------
__global__ void gather_kernel(const int* __restrict__ idx,
                              const float* __restrict__ emb,
                              const float* __restrict__ other) {
    const int t = blockIdx.x;
    const int j = threadIdx.x;            // 0..319
    float v;
    if (j < HID) v = emb[(size_t)idx[t] * HID + j];
    else         v = other[t * 20 + (j - HID)];
    g_X[t * DIN + j] = v;
}

// ---------------- 2) input GEMM: A[dir][t][r] = X[t]·Wi[r] + bi[r] + bh[r] ----
// M=2048 (t), N=1200 (r), K=320. Tiles 64x64x32, 256 threads, 4x4 microtile.
__global__ void __launch_bounds__(256) gemm_in_kernel(
    const float* __restrict__ Wf, const float* __restrict__ Wb,
    const float* __restrict__ bif, const float* __restrict__ bhf,
    const float* __restrict__ bib, const float* __restrict__ bhb) {
    const int dir = blockIdx.z;
    const float* __restrict__ W  = dir ? Wb  : Wf;
    const float* __restrict__ b1 = dir ? bib : bif;
    const float* __restrict__ b2 = dir ? bhb : bhf;
    float* __restrict__ A = g_A + (size_t)dir * T_LEN * G4;

    __shared__ __align__(16) float Xs[32][68];  // [k][m]
    __shared__ __align__(16) float Ws[32][68];  // [k][n]

    const int tid = threadIdx.x;
    const int tx = tid & 15, ty = tid >> 4;
    const int m0 = blockIdx.y * 64, n0 = blockIdx.x * 64;

    float acc[4][4];
#pragma unroll
    for (int i = 0; i < 4; i++)
#pragma unroll
        for (int j = 0; j < 4; j++) acc[i][j] = 0.f;

    for (int k0 = 0; k0 < DIN; k0 += 32) {
#pragma unroll
        for (int it = 0; it < 2; ++it) {
            int v   = tid + it * 256;   // 0..511 float4 slots per tile
            int row = v >> 3;           // 0..63
            int c4  = v & 7;            // float4 within 32-wide k chunk
            float4 x4 = *(const float4*)&g_X[(size_t)(m0 + row) * DIN + k0 + c4 * 4];
            Xs[c4 * 4 + 0][row] = x4.x; Xs[c4 * 4 + 1][row] = x4.y;
            Xs[c4 * 4 + 2][row] = x4.z; Xs[c4 * 4 + 3][row] = x4.w;
            int wr = n0 + row;
            float4 w4 = make_float4(0.f, 0.f, 0.f, 0.f);
            if (wr < G4) w4 = *(const float4*)&W[(size_t)wr * DIN + k0 + c4 * 4];
            Ws[c4 * 4 + 0][row] = w4.x; Ws[c4 * 4 + 1][row] = w4.y;
            Ws[c4 * 4 + 2][row] = w4.z; Ws[c4 * 4 + 3][row] = w4.w;
        }
        __syncthreads();
#pragma unroll
        for (int kk = 0; kk < 32; kk++) {
            float4 xr = *(const float4*)&Xs[kk][ty * 4];
            float4 wr = *(const float4*)&Ws[kk][tx * 4];
            float xv[4] = {xr.x, xr.y, xr.z, xr.w};
            float wv[4] = {wr.x, wr.y, wr.z, wr.w};
#pragma unroll
            for (int i = 0; i < 4; i++)
#pragma unroll
                for (int j = 0; j < 4; j++) acc[i][j] = fmaf(xv[i], wv[j], acc[i][j]);
        }
        __syncthreads();
    }
#pragma unroll
    for (int i = 0; i < 4; i++) {
        int m = m0 + ty * 4 + i;
#pragma unroll
        for (int j = 0; j < 4; j++) {
            int n = n0 + tx * 4 + j;
            if (n < G4) A[(size_t)m * G4 + n] = acc[i][j] + b1[n] + b2[n];
        }
    }
}

// ---------------- profiler slot-shift: no-op launch so lstm lands in the
// ncu-captured position (the captured slot held the 4th launch = feats) ------
__global__ void noop_kernel() {}

// ---------------- 3) BiLSTM recurrence: 2 clusters x 8 CTAs x 512 threads ------
// R5 cluster-barrier design (2952.6 us measured). The R14 mbarrier protocol
// regressed to 6027 us (16-warp try_wait contention + per-step fence drain)
// and is retired.
__global__ __launch_bounds__(512, 1) __cluster_dims__(8, 1, 1)
void lstm_kernel(const float* __restrict__ Whf, const float* __restrict__ Whb,
                 const float* __restrict__ h0,  const float* __restrict__ c0) {
    const int dir = blockIdx.x >> 3;
    unsigned crank;
    asm("mov.u32 %0, %%cluster_ctarank;" : "=r"(crank));
    const int Hc    = (crank < 4) ? 38 : 37;
    const int start = (crank < 4) ? 38 * (int)crank : 152 + 37 * ((int)crank - 4);
    const int NROWS = 4 * Hc;

    const float* __restrict__ Wh    = dir ? Whb : Whf;
    const float* __restrict__ Abase = g_A  + (size_t)dir * T_LEN * G4;
    float*       __restrict__ HS    = g_HS + (size_t)dir * T_LEN * HID;

    __shared__ __align__(16) float hbuf[2][300];   // h double buffer (300 = 3*100)
    __shared__ float part[3][160];                 // per-k-chunk partial sums
    __shared__ float a_s[160];                     // staged input activations

    const int tid  = threadIdx.x;
    const int w    = tid >> 5, lane = tid & 31;
    const bool wact = (w < 15);
    const int q    = wact ? (w / 5) : 0;           // k-chunk 0..2
    const int rw   = w % 5;                        // row-warp 0..4
    const int rloc = rw * 32 + lane;               // 0..159
    const bool active = wact && (rloc < NROWS);

    int gg = 0, kk = 0;
    if (active) { gg = rloc / Hc; kk = rloc - gg * Hc; }
    const int rglobal = gg * HID + start + kk;     // gate row 0..1199
    const bool loader = (q == 0) && active;        // this thread fetches A each step

    // preload Wh slice into registers as 50 packed f32x2 (zeros when inactive)
    unsigned long long w2[50];
    {
        const float* wrow = Wh + (size_t)rglobal * HID + q * 100;
#pragma unroll
        for (int i = 0; i < 25; i++) {
            float4 wv = make_float4(0.f, 0.f, 0.f, 0.f);
            if (active) wv = *(const float4*)(wrow + i * 4);
            unsigned long long lo, hi;
            memcpy(&lo, &wv.x, 8); memcpy(&hi, &wv.z, 8);
            w2[2 * i] = lo; w2[2 * i + 1] = hi;
        }
    }

    // shared-space addresses of the push slot in both h buffers (loop-invariant)
    unsigned la0 = 0, la1 = 0;
    if (tid < Hc) {
        asm("{ .reg .u64 u; cvta.to.shared.u64 u, %1; cvt.u32.u64 %0, u; }"
            : "=r"(la0) : "l"((void*)&hbuf[0][start + tid]));
        asm("{ .reg .u64 u; cvta.to.shared.u64 u, %1; cvt.u32.u64 %0, u; }"
            : "=r"(la1) : "l"((void*)&hbuf[1][start + tid]));
    }

    // init h buffers + c register
    for (int j = tid; j < 300; j += 512) {
        hbuf[0][j] = h0[dir * HID + j];
        hbuf[1][j] = 0.f;
    }
    float creg = (tid < Hc) ? c0[dir * HID + start + tid] : 0.f;
    __syncthreads();
    asm volatile("barrier.cluster.arrive.aligned;" ::: "memory");
    asm volatile("barrier.cluster.wait.aligned;"  ::: "memory");

    // prefetch A for step 0
    float a_val = 0.f;
    if (loader) a_val = __ldg(Abase + (size_t)(dir ? (T_LEN - 1) : 0) * G4 + rglobal);

    int p = 0;
    for (int t = 0; t < T_LEN; ++t) {
        // GEMV partial: packed f32x2 FMA, h chunk via broadcast LDS.128
        const ulonglong2* hv = (const ulonglong2*)(&hbuf[p][q * 100]);
        unsigned long long a0 = 0, a1 = 0;   // (0.0f,0.0f) bit pattern
#pragma unroll
        for (int i = 0; i < 25; i++) {
            ulonglong2 hh = hv[i];
            asm("fma.rn.f32x2 %0, %1, %2, %0;" : "+l"(a0) : "l"(w2[2 * i]),     "l"(hh.x));
            asm("fma.rn.f32x2 %0, %1, %2, %0;" : "+l"(a1) : "l"(w2[2 * i + 1]), "l"(hh.y));
        }
        if (wact) {
            float2 f0, f1;
            memcpy(&f0, &a0, 8); memcpy(&f1, &a1, 8);
            part[q][rloc] = (f0.x + f0.y) + (f1.x + f1.y);
            if (loader) a_s[rloc] = a_val;
        }
        __syncthreads();

        // gate assembly + elementwise update for this CTA's hidden slice
        if (tid < Hc) {
            float pre[4];
#pragma unroll
            for (int g = 0; g < 4; g++) {
                int r = g * Hc + tid;
                pre[g] = a_s[r] + part[0][r] + part[1][r] + part[2][r];
            }
            // fast sigmoid / tanh (MUFU ex2 + fast division)
            float ig = __fdividef(1.f, 1.f + __expf(-pre[0]));
            float fg = __fdividef(1.f, 1.f + __expf(-pre[1]));
            float gv = 1.f - __fdividef(2.f, __expf(2.f * pre[2]) + 1.f);
            float og = __fdividef(1.f, 1.f + __expf(-pre[3]));
            creg = fg * creg + ig * gv;
            float hn = og * (1.f - __fdividef(2.f, __expf(2.f * creg) + 1.f));

            // push h element to every CTA in the cluster first, then global store
            unsigned la = (p ? la0 : la1);         // writing hbuf[p^1]
#pragma unroll
            for (int r = 0; r < 8; r++) {
                unsigned ra;
                asm("mapa.shared::cluster.u32 %0, %1, %2;" : "=r"(ra) : "r"(la), "r"(r));
                asm volatile("st.shared::cluster.f32 [%0], %1;" :: "r"(ra), "f"(hn));
            }
            const int tA = dir ? (T_LEN - 1 - t) : t;
            HS[(size_t)tA * HID + start + tid] = hn;
        }

        asm volatile("barrier.cluster.arrive.aligned;" ::: "memory");

        // prefetch next step's A value in the barrier's shadow
        if (loader && t + 1 < T_LEN) {
            const int tN = dir ? (T_LEN - 2 - t) : (t + 1);
            a_val = __ldg(Abase + (size_t)tN * G4 + rglobal);
        }

        asm volatile("barrier.cluster.wait.aligned;"  ::: "memory");
        p ^= 1;
    }
}

// ---------------- 4) emission feats: feats[t][n] = concat(fw,bw)[t] . W_tag[n] + b
// float4-vectorized loads (75 float4 per 300-float half; rows are 16B-aligned).
__global__ void __launch_bounds__(384) feats_kernel(const float* __restrict__ Wt,
                                                    const float* __restrict__ bt) {
    const int t = blockIdx.x;
    const int n = threadIdx.x >> 5;   // 0..11 (one warp per tag)
    const int lane = threadIdx.x & 31;
    const float4* hf4 = (const float4*)(g_HS + (size_t)t * HID);
    const float4* hb4 = (const float4*)(g_HS + (size_t)T_LEN * HID + (size_t)t * HID);
    const float4* wf4 = (const float4*)(Wt + (size_t)n * 2 * HID);
    const float4* wb4 = (const float4*)(Wt + (size_t)n * 2 * HID + HID);
    float s = 0.f;
    for (int j = lane; j < HID / 4; j += 32) {     // 75 float4
        float4 h4 = hf4[j], w4 = wf4[j];
        s = fmaf(h4.x, w4.x, s); s = fmaf(h4.y, w4.y, s);
        s = fmaf(h4.z, w4.z, s); s = fmaf(h4.w, w4.w, s);
    }
    for (int j = lane; j < HID / 4; j += 32) {
        float4 h4 = hb4[j], w4 = wb4[j];
        s = fmaf(h4.x, w4.x, s); s = fmaf(h4.y, w4.y, s);
        s = fmaf(h4.z, w4.z, s); s = fmaf(h4.w, w4.w, s);
    }
#pragma unroll
    for (int o = 16; o; o >>= 1) s += __shfl_down_sync(0xffffffffu, s, o);
    if (lane == 0) g_F[t * NTAGS + n] = s + bt[n];
}

// ---------------- 5) Viterbi + backtrace: single warp ----------------
// Emission loads are distance-2 prefetched so the serial loop runs at the
// SHFL + select-tree compute floor instead of exposing L2 latency each step.
__global__ void viterbi_kernel(const float* __restrict__ trans,
                               float* __restrict__ outf, int out_size) {
    __shared__ unsigned char bps[T_LEN * NTAGS];   // 24 KB backpointers
    const int lane = threadIdx.x;
    const bool on = lane < NTAGS;

    float trow[NTAGS];
#pragma unroll
    for (int pp = 0; pp < NTAGS; pp++) trow[pp] = on ? trans[lane * NTAGS + pp] : NEGV;
    float tstop = on ? trans[STOP_TAG * NTAGS + lane] : NEGV;
    float fv = (lane == START_TAG) ? 0.f : NEGV;

    const float* __restrict__ Fp = on ? (g_F + lane) : g_F;   // lane's column
    float featC = __ldg(Fp);                                   // feat(0)
    float featN = __ldg(Fp + NTAGS);                           // feat(1)

    for (int t = 0; t < T_LEN; t++) {
        float featP = (t + 2 < T_LEN) ? __ldg(Fp + (size_t)(t + 2) * NTAGS) : 0.f;

        float s[NTAGS];
#pragma unroll
        for (int pp = 0; pp < NTAGS; pp++)
            s[pp] = __shfl_sync(0xffffffffu, fv, pp) + trow[pp];

        // argmax with JAX first-index tie semantics (strict >, lower index wins)
        float v0 = s[0];  int i0 = 0;  if (s[1]  > v0) { v0 = s[1];  i0 = 1; }
        float v1 = s[2];  int i1 = 2;  if (s[3]  > v1) { v1 = s[3];  i1 = 3; }
        float v2 = s[4];  int i2 = 4;  if (s[5]  > v2) { v2 = s[5];  i2 = 5; }
        float v3 = s[6];  int i3 = 6;  if (s[7]  > v3) { v3 = s[7];  i3 = 7; }
        float v4 = s[8];  int i4 = 8;  if (s[9]  > v4) { v4 = s[9];  i4 = 9; }
        float v5 = s[10]; int i5 = 10; if (s[11] > v5) { v5 = s[11]; i5 = 11; }
        if (v1 > v0) { v0 = v1; i0 = i1; }
        if (v3 > v2) { v2 = v3; i2 = i3; }
        if (v5 > v4) { v4 = v5; i4 = i5; }
        if (v2 > v0) { v0 = v2; i0 = i2; }
        if (v4 > v0) { v0 = v4; i0 = i4; }

        if (on) {
            fv = v0 + featC;
            bps[t * NTAGS + lane] = (unsigned char)i0;
        }
        featC = featN;
        featN = featP;
    }

    float tv = fv + tstop;
    float best = __shfl_sync(0xffffffffu, tv, 0);
    int bi = 0;
#pragma unroll
    for (int pp = 1; pp < NTAGS; pp++) {
        float v = __shfl_sync(0xffffffffu, tv, pp);
        if (v > best) { best = v; bi = pp; }
    }

    if (lane == 0) {
        if (out_size == T_LEN + 1) {             // [score, path...] as float32
            outf[0] = best;
            int tg = bi;
            for (int t = T_LEN - 1; t >= 0; t--) {
                outf[1 + t] = (float)tg;
                tg = bps[t * NTAGS + tg];
            }
        } else {                                  // fallback: int32 path only
            int* oi = (int*)outf;
            int tg = bi;
            for (int t = T_LEN - 1; t >= 0; t--) {
                oi[t] = tg;
                tg = bps[t * NTAGS + tg];
            }
        }
    }
}

// ---------------- launch ----------------
extern "C" void kernel_launch(void* const* d_in, const int* in_sizes, int n_in,
                              void* d_out, int out_size) {
    const int*   indices = (const int*)  d_in[0];
    const float* other   = (const float*)d_in[1];
    const float* emb     = (const float*)d_in[2];
    const float* Wi_f    = (const float*)d_in[3];
    const float* Wh_f    = (const float*)d_in[4];
    const float* bi_f    = (const float*)d_in[5];
    const float* bh_f    = (const float*)d_in[6];
    const float* Wi_b    = (const float*)d_in[7];
    const float* Wh_b    = (const float*)d_in[8];
    const float* bi_b    = (const float*)d_in[9];
    const float* bh_b    = (const float*)d_in[10];
    const float* W_tag   = (const float*)d_in[11];
    const float* b_tag   = (const float*)d_in[12];
    const float* trans   = (const float*)d_in[13];
    const float* h0      = (const float*)d_in[14];
    const float* c0      = (const float*)d_in[15];

    gather_kernel<<<T_LEN, DIN>>>(indices, emb, other);
    gemm_in_kernel<<<dim3(19, 32, 2), 256>>>(Wi_f, Wi_b, bi_f, bh_f, bi_b, bh_b);
    noop_kernel<<<1, 32>>>();   // slot-shift: puts lstm_kernel in the ncu capture position
    lstm_kernel<<<16, 512>>>(Wh_f, Wh_b, h0, c0);
    feats_kernel<<<T_LEN, 384>>>(W_tag, b_tag);
    viterbi_kernel<<<1, 32>>>(trans, (float*)d_out, out_size);
}